// round 3
// baseline (speedup 1.0000x reference)
#include <cuda_runtime.h>
#include <cstdint>

// ---------------------------------------------------------------------------
// xLSTM cell fused kernel, portable sm_103 path (no "a" features):
//   G[8192,4096] = [x|h] @ [W|U]^T  via mma.sync.m16n8k8.tf32 (legacy HMMA),
//   then sigmoid/tanh gating epilogue, all in one kernel.
//
// CTA tile: BM=128 batch rows x (4 gates x 64 h-cols) = 256 N-cols.
// 256 threads, 8 warps as 2(m) x 4(n); warp tile 64x64 where the 64 N-cols
// = 4 gates x 16 h-cols  ==> all 4 gates of an (m,h) output live in the SAME
// thread's C fragments -> thread-local epilogue, no smem exchange.
// K loop: 64 chunks of BK=32 (first 32 = x*W, last 32 = h*U).
// 4-stage cp.async pipeline, 48KB/stage (A 16KB + B 32KB), SW128 swizzle,
// ldmatrix.x4.b16 operand fetch (maps exactly to tf32 fragments).
// Grid: 64 m-tiles x 16 h-tiles = 1024 CTAs.
// ---------------------------------------------------------------------------

#define NTHREADS 256
#define STAGES 4
#define A_TILE_BYTES 16384            // 128 rows x 128B (32 tf32)
#define B_TILE_BYTES 32768            // 256 rows x 128B
#define STAGE_BYTES  (A_TILE_BYTES + B_TILE_BYTES)   // 49152
#define SMEM_TOTAL   (STAGES * STAGE_BYTES)          // 196608

#define SWZ(o) ((o) ^ (((o) >> 3) & 0x70))

static __device__ __forceinline__ uint32_t smem_u32(const void* p) {
    uint32_t a;
    asm("{ .reg .u64 t; cvta.to.shared.u64 t, %1; cvt.u32.u64 %0, t; }"
        : "=r"(a) : "l"(p));
    return a;
}

#define CP_ASYNC16(dst, src) \
    asm volatile("cp.async.cg.shared.global [%0], [%1], 16;" :: "r"(dst), "l"(src) : "memory")
#define CP_COMMIT() asm volatile("cp.async.commit_group;" ::: "memory")
#define CP_WAIT2()  asm volatile("cp.async.wait_group 2;" ::: "memory")

#define LDMATRIX_X4(r0, r1, r2, r3, addr) \
    asm volatile("ldmatrix.sync.aligned.m8n8.x4.shared.b16 {%0,%1,%2,%3}, [%4];" \
                 : "=r"(r0), "=r"(r1), "=r"(r2), "=r"(r3) : "r"(addr))

#define MMA_TF32(d, a, b) \
    asm volatile("mma.sync.aligned.m16n8k8.row.col.f32.tf32.tf32.f32 " \
                 "{%0,%1,%2,%3}, {%4,%5,%6,%7}, {%8,%9}, {%0,%1,%2,%3};" \
                 : "+f"((d)[0]), "+f"((d)[1]), "+f"((d)[2]), "+f"((d)[3]) \
                 : "r"((a)[0]), "r"((a)[1]), "r"((a)[2]), "r"((a)[3]), \
                   "r"((b)[0]), "r"((b)[1]))

static __device__ __forceinline__ float sigmoidf_(float v) {
    return 1.0f / (1.0f + __expf(-v));
}
static __device__ __forceinline__ float tanhf_(float v) {
    // tanh(x) = 1 - 2/(exp(2x)+1); correct saturation at both ends with __expf
    return 1.0f - 2.0f / (__expf(2.0f * v) + 1.0f);
}

__global__ void __launch_bounds__(NTHREADS, 1) xlstm_tf32_mma_kernel(
    const float* __restrict__ x, const float* __restrict__ hprev,
    const float* __restrict__ cprev,
    const float* __restrict__ W, const float* __restrict__ bW,
    const float* __restrict__ U, const float* __restrict__ bU,
    float* __restrict__ o1, float* __restrict__ o2, float* __restrict__ oc)
{
    extern __shared__ char smem[];
    const uint32_t sbase = smem_u32(smem);

    const int tid  = threadIdx.x;
    const int lane = tid & 31;
    const int warp = tid >> 5;
    const int warp_m = warp >> 2;      // 0..1 : 64 m-rows each
    const int warp_n = warp & 3;       // 0..3 : 16 h-cols each (x4 gates)

    const int bid = blockIdx.x;
    const int m0 = (bid >> 4) << 7;    // 64 m-tiles of 128
    const int h0 = (bid & 15) << 6;    // 16 h-tiles of 64

    // ---- cp.async per-thread offsets (slot j covers row r = slot/8, 16B chunk cq) ----
    uint32_t dst[8];
    int srcB[8];
    int srcA[4];
#pragma unroll
    for (int j = 0; j < 8; j++) {
        int slot = tid + j * NTHREADS;       // 0..2047
        int r = slot >> 3, cq = slot & 7;
        dst[j] = SWZ((uint32_t)(r * 128 + cq * 16));
        int g = r >> 6, hc = r & 63;         // B rows: gate-major [4][64]
        srcB[j] = g * 1048576 + hc * 1024 + cq * 4;
        if (j < 4) srcA[j] = r * 1024 + cq * 4;
    }

    // ---- ldmatrix per-thread address components ----
    // A fragment (m16k8): lanes 0-15 -> rows 0..15 @ k-chunk lo, lanes 16-31 -> same rows @ k-chunk hi
    uint32_t aRow[4], aXor[4];
#pragma unroll
    for (int mt = 0; mt < 4; mt++) {
        uint32_t row = (uint32_t)(warp_m * 64 + mt * 16 + (lane & 15)) * 128u;
        aRow[mt] = row;
        aXor[mt] = (row >> 3) & 0x70;
    }
    // B fragment pair (two n8 tiles = one gate's jp=0/1): lanes>>4 selects jp tile,
    // (lane>>3)&1 selects k half within tile.
    uint32_t bRow[4], bXor[4];
#pragma unroll
    for (int g = 0; g < 4; g++) {
        uint32_t row = (uint32_t)(g * 64 + warp_n * 16 + ((lane >> 4) << 3) + (lane & 7)) * 128u;
        bRow[g] = row;
        bXor[g] = (row >> 3) & 0x70;
    }
    const uint32_t aChunkSel = (uint32_t)((lane >> 4) << 4);        // 0 or 16
    const uint32_t bChunkSel = (uint32_t)(((lane >> 3) & 1) << 4);  // 0 or 16

    float acc[4][8][4];
#pragma unroll
    for (int mt = 0; mt < 4; mt++)
#pragma unroll
        for (int nt = 0; nt < 8; nt++)
#pragma unroll
            for (int r = 0; r < 4; r++) acc[mt][nt][r] = 0.0f;

    // ---- pipeline prologue: prefetch stages for kc = 0,1,2 ----
#pragma unroll
    for (int p = 0; p < STAGES - 1; p++) {
        const float* asrc = (p < 32) ? x : hprev;
        const float* bsrc = (p < 32) ? W : U;
        int k0 = (p & 31) << 5;
        const float* ap = asrc + (size_t)m0 * 1024 + k0;
        const float* bp = bsrc + (size_t)h0 * 1024 + k0;
        uint32_t sA = sbase + (uint32_t)p * STAGE_BYTES;
        uint32_t sB = sA + A_TILE_BYTES;
#pragma unroll
        for (int j = 0; j < 4; j++) CP_ASYNC16(sA + dst[j], ap + srcA[j]);
#pragma unroll
        for (int j = 0; j < 8; j++) CP_ASYNC16(sB + dst[j], bp + srcB[j]);
        CP_COMMIT();
    }

    // ---- mainloop: 64 K-chunks ----
#pragma unroll 1
    for (int kc = 0; kc < 64; kc++) {
        CP_WAIT2();          // stage kc resident
        __syncthreads();     // all threads' copies visible; prev compute done

        // issue loads for kc+3 into buffer (kc+3)%STAGES
        {
            int kn = kc + 3;
            if (kn < 64) {
                const float* asrc = (kn < 32) ? x : hprev;
                const float* bsrc = (kn < 32) ? W : U;
                int k0 = (kn & 31) << 5;
                const float* ap = asrc + (size_t)m0 * 1024 + k0;
                const float* bp = bsrc + (size_t)h0 * 1024 + k0;
                uint32_t sA = sbase + (uint32_t)(kn & (STAGES - 1)) * STAGE_BYTES;
                uint32_t sB = sA + A_TILE_BYTES;
#pragma unroll
                for (int j = 0; j < 4; j++) CP_ASYNC16(sA + dst[j], ap + srcA[j]);
#pragma unroll
                for (int j = 0; j < 8; j++) CP_ASYNC16(sB + dst[j], bp + srcB[j]);
            }
            CP_COMMIT();     // empty group when kn >= 64 keeps wait counts aligned
        }

        // compute on stage kc%STAGES
        const uint32_t sA = sbase + (uint32_t)(kc & (STAGES - 1)) * STAGE_BYTES;
        const uint32_t sB = sA + A_TILE_BYTES;

#pragma unroll
        for (int s = 0; s < 4; s++) {
            const uint32_t aCh = (uint32_t)(s * 32) + aChunkSel;  // byte offset of 16B chunk
            const uint32_t bCh = (uint32_t)(s * 32) + bChunkSel;

            uint32_t a[4][4];
#pragma unroll
            for (int mt = 0; mt < 4; mt++)
                LDMATRIX_X4(a[mt][0], a[mt][1], a[mt][2], a[mt][3],
                            sA + aRow[mt] + (aCh ^ aXor[mt]));

            uint32_t b[8][2];
#pragma unroll
            for (int g = 0; g < 4; g++)
                LDMATRIX_X4(b[g * 2][0], b[g * 2][1], b[g * 2 + 1][0], b[g * 2 + 1][1],
                            sB + bRow[g] + (bCh ^ bXor[g]));

#pragma unroll
            for (int mt = 0; mt < 4; mt++)
#pragma unroll
                for (int nt = 0; nt < 8; nt++)
                    MMA_TF32(acc[mt][nt], a[mt], b[nt]);
        }
    }

    // ---- epilogue: thread-local (all 4 gates live in this thread's fragments) ----
    // C frag mapping: c0=(row l/4, col 2(l%4)); c1=+1col; c2=+8row; c3=+8row,+1col
    // n-tile nt = gate*2 + jp ; h-col = h0 + warp_n*16 + jp*8 + 2*(lane%4) + e
    const int hc0 = h0 + warp_n * 16 + 2 * (lane & 3);

    float bsum[4][2][2];
#pragma unroll
    for (int g = 0; g < 4; g++)
#pragma unroll
        for (int jp = 0; jp < 2; jp++)
#pragma unroll
            for (int e = 0; e < 2; e++) {
                int col = hc0 + jp * 8 + e;
                bsum[g][jp][e] = bW[g * 1024 + col] + bU[g * 1024 + col];
            }

#pragma unroll
    for (int mt = 0; mt < 4; mt++) {
#pragma unroll
        for (int rh = 0; rh < 2; rh++) {
            int m = m0 + warp_m * 64 + mt * 16 + (lane >> 2) + rh * 8;
            size_t rowbase = (size_t)m * 1024;
#pragma unroll
            for (int jp = 0; jp < 2; jp++) {
                int col = hc0 + jp * 8;
                float2 cold = *reinterpret_cast<const float2*>(cprev + rowbase + col);

                float hn[2], cn[2];
#pragma unroll
                for (int e = 0; e < 2; e++) {
                    int rr = rh * 2 + e;
                    float gi = acc[mt][0 + jp][rr] + bsum[0][jp][e];
                    float gf = acc[mt][2 + jp][rr] + bsum[1][jp][e];
                    float go = acc[mt][4 + jp][rr] + bsum[2][jp][e];
                    float gc = acc[mt][6 + jp][rr] + bsum[3][jp][e];
                    float iv = sigmoidf_(gi);
                    float fv = sigmoidf_(gf);
                    float ov = sigmoidf_(go);
                    float ch = tanhf_(gc);
                    float cold_e = (e == 0) ? cold.x : cold.y;
                    float cv = fv * cold_e + iv * ch;
                    cn[e] = cv;
                    hn[e] = ov * tanhf_(cv);
                }

                float2 hv = make_float2(hn[0], hn[1]);
                *reinterpret_cast<float2*>(o1 + rowbase + col) = hv;
                if (o2) *reinterpret_cast<float2*>(o2 + rowbase + col) = hv;
                if (oc) *reinterpret_cast<float2*>(oc + rowbase + col) = make_float2(cn[0], cn[1]);
            }
        }
    }
}

extern "C" void kernel_launch(void* const* d_in, const int* in_sizes, int n_in,
                              void* d_out, int out_size) {
    const float* x  = (const float*)d_in[0];
    const float* h  = (const float*)d_in[1];
    const float* c  = (const float*)d_in[2];
    const float* W  = (const float*)d_in[3];
    const float* bW = (const float*)d_in[4];
    const float* U  = (const float*)d_in[5];
    const float* bU = (const float*)d_in[6];
    float* out = (float*)d_out;

    const long long BH = 8192LL * 1024LL;
    float* o1 = out;
    float* o2 = nullptr;
    float* oc = nullptr;
    if ((long long)out_size >= 3 * BH) {          // (h_new, h_new, c_new)
        o2 = out + BH;
        oc = out + 2 * BH;
    } else if ((long long)out_size >= 2 * BH) {   // (h_new, c_new)
        oc = out + BH;
    }

    cudaFuncSetAttribute(xlstm_tf32_mma_kernel,
                         cudaFuncAttributeMaxDynamicSharedMemorySize, SMEM_TOTAL);
    xlstm_tf32_mma_kernel<<<1024, NTHREADS, SMEM_TOTAL>>>(x, h, c, W, bW, U, bU, o1, o2, oc);
}

// round 4
// speedup vs baseline: 1.0548x; 1.0548x over previous
#include <cuda_runtime.h>
#include <cstdint>

// ---------------------------------------------------------------------------
// xLSTM cell fused kernel, portable sm_103 path (no "a" features):
//   G[8192,4096] = [x|h] @ [W|U]^T  via mma.sync.m16n8k8.tf32 (legacy HMMA),
//   then sigmoid/tanh gating epilogue, all in one kernel.
//
// R4 change vs R3: BK=64 mega-chunks (2 x 48KB half-stages), 2 buffers
// (192KB smem), ONE __syncthreads + one wait_group per 64 K-columns
// (was per 32). Halves barrier/fence count, doubles compute per sync to
// shrink tensor-pipe bubbles (ncu R3: tensor=59%, mem idle).
//
// CTA tile: BM=128 batch rows x (4 gates x 64 h-cols) = 256 N-cols.
// 256 threads, 8 warps as 2(m) x 4(n); warp tile 64x64 where the 64 N-cols
// = 4 gates x 16 h-cols ==> all 4 gates of an (m,h) output live in the SAME
// thread's C fragments -> thread-local epilogue, no smem exchange.
// Grid: 64 m-tiles x 16 h-tiles = 1024 CTAs.
// ---------------------------------------------------------------------------

#define NTHREADS 256
#define A_TILE_BYTES 16384            // 128 rows x 128B (32 tf32)
#define B_TILE_BYTES 32768            // 256 rows x 128B
#define HALF_BYTES   (A_TILE_BYTES + B_TILE_BYTES)   // 49152 (one BK=32 chunk)
#define STAGE_BYTES  (2 * HALF_BYTES)                // 98304 (one BK=64 mega)
#define SMEM_TOTAL   (2 * STAGE_BYTES)               // 196608

#define SWZ(o) ((o) ^ (((o) >> 3) & 0x70))

static __device__ __forceinline__ uint32_t smem_u32(const void* p) {
    uint32_t a;
    asm("{ .reg .u64 t; cvta.to.shared.u64 t, %1; cvt.u32.u64 %0, t; }"
        : "=r"(a) : "l"(p));
    return a;
}

#define CP_ASYNC16(dst, src) \
    asm volatile("cp.async.cg.shared.global [%0], [%1], 16;" :: "r"(dst), "l"(src) : "memory")
#define CP_COMMIT() asm volatile("cp.async.commit_group;" ::: "memory")
#define CP_WAIT0()  asm volatile("cp.async.wait_group 0;" ::: "memory")

#define LDMATRIX_X4(r0, r1, r2, r3, addr) \
    asm volatile("ldmatrix.sync.aligned.m8n8.x4.shared.b16 {%0,%1,%2,%3}, [%4];" \
                 : "=r"(r0), "=r"(r1), "=r"(r2), "=r"(r3) : "r"(addr))

#define MMA_TF32(d, a, b) \
    asm volatile("mma.sync.aligned.m16n8k8.row.col.f32.tf32.tf32.f32 " \
                 "{%0,%1,%2,%3}, {%4,%5,%6,%7}, {%8,%9}, {%0,%1,%2,%3};" \
                 : "+f"((d)[0]), "+f"((d)[1]), "+f"((d)[2]), "+f"((d)[3]) \
                 : "r"((a)[0]), "r"((a)[1]), "r"((a)[2]), "r"((a)[3]), \
                   "r"((b)[0]), "r"((b)[1]))

static __device__ __forceinline__ float sigmoidf_(float v) {
    return 1.0f / (1.0f + __expf(-v));
}
static __device__ __forceinline__ float tanhf_(float v) {
    // tanh(x) = 1 - 2/(exp(2x)+1); correct saturation at both ends with __expf
    return 1.0f - 2.0f / (__expf(2.0f * v) + 1.0f);
}

// Load one BK=32 chunk (A tile + 4-gate B tile) into one half-stage.
static __device__ __forceinline__ void load_chunk32(
    int kc, uint32_t half_sm,
    const float* __restrict__ x, const float* __restrict__ hprev,
    const float* __restrict__ W, const float* __restrict__ U,
    int m0, int h0, const uint32_t* dst, const int* srcA, const int* srcB)
{
    const float* asrc = (kc < 32) ? x : hprev;
    const float* bsrc = (kc < 32) ? W : U;
    int k0 = (kc & 31) << 5;
    const float* ap = asrc + (size_t)m0 * 1024 + k0;
    const float* bp = bsrc + (size_t)h0 * 1024 + k0;
    uint32_t sB = half_sm + A_TILE_BYTES;
#pragma unroll
    for (int j = 0; j < 4; j++) CP_ASYNC16(half_sm + dst[j], ap + srcA[j]);
#pragma unroll
    for (int j = 0; j < 8; j++) CP_ASYNC16(sB + dst[j], bp + srcB[j]);
}

__global__ void __launch_bounds__(NTHREADS, 1) xlstm_tf32_mma_kernel(
    const float* __restrict__ x, const float* __restrict__ hprev,
    const float* __restrict__ cprev,
    const float* __restrict__ W, const float* __restrict__ bW,
    const float* __restrict__ U, const float* __restrict__ bU,
    float* __restrict__ o1, float* __restrict__ o2, float* __restrict__ oc)
{
    extern __shared__ char smem[];
    const uint32_t sbase = smem_u32(smem);

    const int tid  = threadIdx.x;
    const int lane = tid & 31;
    const int warp = tid >> 5;
    const int warp_m = warp >> 2;      // 0..1 : 64 m-rows each
    const int warp_n = warp & 3;       // 0..3 : 16 h-cols each (x4 gates)

    const int bid = blockIdx.x;
    const int m0 = (bid >> 4) << 7;    // 64 m-tiles of 128
    const int h0 = (bid & 15) << 6;    // 16 h-tiles of 64

    // ---- cp.async per-thread offsets (slot j covers row r = slot/8, 16B chunk cq) ----
    uint32_t dst[8];
    int srcB[8];
    int srcA[4];
#pragma unroll
    for (int j = 0; j < 8; j++) {
        int slot = tid + j * NTHREADS;       // 0..2047
        int r = slot >> 3, cq = slot & 7;
        dst[j] = SWZ((uint32_t)(r * 128 + cq * 16));
        int g = r >> 6, hc = r & 63;         // B rows: gate-major [4][64]
        srcB[j] = g * 1048576 + hc * 1024 + cq * 4;
        if (j < 4) srcA[j] = r * 1024 + cq * 4;
    }

    // ---- ldmatrix per-thread address components ----
    // A fragment (m16k8): lanes 0-15 -> rows @ k-chunk lo, lanes 16-31 -> rows @ k-chunk hi
    uint32_t aRow[4], aXor[4];
#pragma unroll
    for (int mt = 0; mt < 4; mt++) {
        uint32_t row = (uint32_t)(warp_m * 64 + mt * 16 + (lane & 15)) * 128u;
        aRow[mt] = row;
        aXor[mt] = (row >> 3) & 0x70;
    }
    // B fragment pair (two n8 tiles = one gate's jp=0/1): lane>>4 selects jp tile,
    // (lane>>3)&1 selects k half within tile.
    uint32_t bRow[4], bXor[4];
#pragma unroll
    for (int g = 0; g < 4; g++) {
        uint32_t row = (uint32_t)(g * 64 + warp_n * 16 + ((lane >> 4) << 3) + (lane & 7)) * 128u;
        bRow[g] = row;
        bXor[g] = (row >> 3) & 0x70;
    }
    const uint32_t aChunkSel = (uint32_t)((lane >> 4) << 4);        // 0 or 16
    const uint32_t bChunkSel = (uint32_t)(((lane >> 3) & 1) << 4);  // 0 or 16

    float acc[4][8][4];
#pragma unroll
    for (int mt = 0; mt < 4; mt++)
#pragma unroll
        for (int nt = 0; nt < 8; nt++)
#pragma unroll
            for (int r = 0; r < 4; r++) acc[mt][nt][r] = 0.0f;

    // ---- prologue: load mega-chunk 0 (BK chunks 0,1) into buffer 0 ----
    load_chunk32(0, sbase, x, hprev, W, U, m0, h0, dst, srcA, srcB);
    load_chunk32(1, sbase + HALF_BYTES, x, hprev, W, U, m0, h0, dst, srcA, srcB);
    CP_COMMIT();

    // ---- mainloop: 32 mega-iterations of BK=64 ----
#pragma unroll 1
    for (int it = 0; it < 32; it++) {
        CP_WAIT0();          // mega it resident (issued one full iteration ago)
        __syncthreads();     // everyone's data visible; prev iter's compute done

        // prefetch mega it+1 into the other buffer (freed by the sync above)
        if (it + 1 < 32) {
            uint32_t nb = sbase + (uint32_t)((it + 1) & 1) * STAGE_BYTES;
            load_chunk32(2 * it + 2, nb, x, hprev, W, U, m0, h0, dst, srcA, srcB);
            load_chunk32(2 * it + 3, nb + HALF_BYTES, x, hprev, W, U, m0, h0, dst, srcA, srcB);
        }
        CP_COMMIT();         // empty group on last iter keeps accounting trivial

        // compute both halves of mega it
        const uint32_t stage = sbase + (uint32_t)(it & 1) * STAGE_BYTES;
#pragma unroll
        for (int half = 0; half < 2; half++) {
            const uint32_t sA = stage + (uint32_t)half * HALF_BYTES;
            const uint32_t sB = sA + A_TILE_BYTES;

#pragma unroll
            for (int s = 0; s < 4; s++) {
                const uint32_t aCh = (uint32_t)(s * 32) + aChunkSel;  // byte off of 16B chunk
                const uint32_t bCh = (uint32_t)(s * 32) + bChunkSel;

                uint32_t a[4][4];
#pragma unroll
                for (int mt = 0; mt < 4; mt++)
                    LDMATRIX_X4(a[mt][0], a[mt][1], a[mt][2], a[mt][3],
                                sA + aRow[mt] + (aCh ^ aXor[mt]));

                uint32_t b[8][2];
#pragma unroll
                for (int g = 0; g < 4; g++)
                    LDMATRIX_X4(b[g * 2][0], b[g * 2][1], b[g * 2 + 1][0], b[g * 2 + 1][1],
                                sB + bRow[g] + (bCh ^ bXor[g]));

#pragma unroll
                for (int mt = 0; mt < 4; mt++)
#pragma unroll
                    for (int nt = 0; nt < 8; nt++)
                        MMA_TF32(acc[mt][nt], a[mt], b[nt]);
            }
        }
    }

    // ---- epilogue: thread-local (all 4 gates live in this thread's fragments) ----
    // C frag mapping: c0=(row l/4, col 2(l%4)); c1=+1col; c2=+8row; c3=+8row,+1col
    // n-tile nt = gate*2 + jp ; h-col = h0 + warp_n*16 + jp*8 + 2*(lane%4) + e
    const int hc0 = h0 + warp_n * 16 + 2 * (lane & 3);

    float bsum[4][2][2];
#pragma unroll
    for (int g = 0; g < 4; g++)
#pragma unroll
        for (int jp = 0; jp < 2; jp++)
#pragma unroll
            for (int e = 0; e < 2; e++) {
                int col = hc0 + jp * 8 + e;
                bsum[g][jp][e] = bW[g * 1024 + col] + bU[g * 1024 + col];
            }

#pragma unroll
    for (int mt = 0; mt < 4; mt++) {
#pragma unroll
        for (int rh = 0; rh < 2; rh++) {
            int m = m0 + warp_m * 64 + mt * 16 + (lane >> 2) + rh * 8;
            size_t rowbase = (size_t)m * 1024;
#pragma unroll
            for (int jp = 0; jp < 2; jp++) {
                int col = hc0 + jp * 8;
                float2 cold = *reinterpret_cast<const float2*>(cprev + rowbase + col);

                float hn[2], cn[2];
#pragma unroll
                for (int e = 0; e < 2; e++) {
                    int rr = rh * 2 + e;
                    float gi = acc[mt][0 + jp][rr] + bsum[0][jp][e];
                    float gf = acc[mt][2 + jp][rr] + bsum[1][jp][e];
                    float go = acc[mt][4 + jp][rr] + bsum[2][jp][e];
                    float gc = acc[mt][6 + jp][rr] + bsum[3][jp][e];
                    float iv = sigmoidf_(gi);
                    float fv = sigmoidf_(gf);
                    float ov = sigmoidf_(go);
                    float ch = tanhf_(gc);
                    float cold_e = (e == 0) ? cold.x : cold.y;
                    float cv = fv * cold_e + iv * ch;
                    cn[e] = cv;
                    hn[e] = ov * tanhf_(cv);
                }

                float2 hv = make_float2(hn[0], hn[1]);
                *reinterpret_cast<float2*>(o1 + rowbase + col) = hv;
                if (o2) *reinterpret_cast<float2*>(o2 + rowbase + col) = hv;
                if (oc) *reinterpret_cast<float2*>(oc + rowbase + col) = make_float2(cn[0], cn[1]);
            }
        }
    }
}

extern "C" void kernel_launch(void* const* d_in, const int* in_sizes, int n_in,
                              void* d_out, int out_size) {
    const float* x  = (const float*)d_in[0];
    const float* h  = (const float*)d_in[1];
    const float* c  = (const float*)d_in[2];
    const float* W  = (const float*)d_in[3];
    const float* bW = (const float*)d_in[4];
    const float* U  = (const float*)d_in[5];
    const float* bU = (const float*)d_in[6];
    float* out = (float*)d_out;

    const long long BH = 8192LL * 1024LL;
    float* o1 = out;
    float* o2 = nullptr;
    float* oc = nullptr;
    if ((long long)out_size >= 3 * BH) {          // (h_new, h_new, c_new)
        o2 = out + BH;
        oc = out + 2 * BH;
    } else if ((long long)out_size >= 2 * BH) {   // (h_new, c_new)
        oc = out + BH;
    }

    cudaFuncSetAttribute(xlstm_tf32_mma_kernel,
                         cudaFuncAttributeMaxDynamicSharedMemorySize, SMEM_TOTAL);
    xlstm_tf32_mma_kernel<<<1024, NTHREADS, SMEM_TOTAL>>>(x, h, c, W, bW, U, bU, o1, o2, oc);
}

// round 5
// speedup vs baseline: 1.1517x; 1.0919x over previous
#include <cuda_runtime.h>
#include <cstdint>

// ---------------------------------------------------------------------------
// xLSTM cell fused kernel, portable sm_103 path (no "a" features):
//   G[8192,4096] = [x|h] @ [W|U]^T  via mma.sync.m16n8k8.tf32,
//   then sigmoid/tanh gating epilogue, all in one kernel.
//
// R5 change vs R4: 2 CTAs/SM. CTA tile halved in N: BM=128 x (4 gates x 32
// h-cols) = 128 N-rows of B. Warp tile 64x32 (4 gates x 8 h-cols), acc = 64
// regs, __launch_bounds__(256,2). 3-stage cp.async pipeline of BK=32 chunks
// (32KB/stage, 96KB/CTA). Grid 2048 = 64 m-tiles x 32 h-tiles.
// Rationale (R4 ncu): tensor=62%, occ=12.5% (2 warps/SMSP) -> LDSM->MMA
// latency exposed; 4 warps/SMSP covers it. Memory has 5x headroom (L2=15%).
// ---------------------------------------------------------------------------

#define NTHREADS 256
#define STAGES 3
#define A_TILE_BYTES 16384            // 128 rows x 128B (32 tf32)
#define B_TILE_BYTES 16384            // 128 rows (4g x 32hc) x 128B
#define STAGE_BYTES  (A_TILE_BYTES + B_TILE_BYTES)   // 32768
#define SMEM_TOTAL   (STAGES * STAGE_BYTES)          // 98304

#define SWZ(o) ((o) ^ (((o) >> 3) & 0x70))

static __device__ __forceinline__ uint32_t smem_u32(const void* p) {
    uint32_t a;
    asm("{ .reg .u64 t; cvta.to.shared.u64 t, %1; cvt.u32.u64 %0, t; }"
        : "=r"(a) : "l"(p));
    return a;
}

#define CP_ASYNC16(dst, src) \
    asm volatile("cp.async.cg.shared.global [%0], [%1], 16;" :: "r"(dst), "l"(src) : "memory")
#define CP_COMMIT() asm volatile("cp.async.commit_group;" ::: "memory")
#define CP_WAIT1()  asm volatile("cp.async.wait_group 1;" ::: "memory")

#define LDMATRIX_X4(r0, r1, r2, r3, addr) \
    asm volatile("ldmatrix.sync.aligned.m8n8.x4.shared.b16 {%0,%1,%2,%3}, [%4];" \
                 : "=r"(r0), "=r"(r1), "=r"(r2), "=r"(r3) : "r"(addr))

#define MMA_TF32_2(d, a, b0, b1) \
    asm volatile("mma.sync.aligned.m16n8k8.row.col.f32.tf32.tf32.f32 " \
                 "{%0,%1,%2,%3}, {%4,%5,%6,%7}, {%8,%9}, {%0,%1,%2,%3};" \
                 : "+f"((d)[0]), "+f"((d)[1]), "+f"((d)[2]), "+f"((d)[3]) \
                 : "r"((a)[0]), "r"((a)[1]), "r"((a)[2]), "r"((a)[3]), \
                   "r"(b0), "r"(b1))

static __device__ __forceinline__ float sigmoidf_(float v) {
    return 1.0f / (1.0f + __expf(-v));
}
static __device__ __forceinline__ float tanhf_(float v) {
    return 1.0f - 2.0f / (__expf(2.0f * v) + 1.0f);
}

// Load one BK=32 chunk (A tile 128x32 + B tile [4g x 32hc] x 32) into a stage.
static __device__ __forceinline__ void load_chunk32(
    int kc, uint32_t stage_sm,
    const float* __restrict__ x, const float* __restrict__ hprev,
    const float* __restrict__ W, const float* __restrict__ U,
    const uint32_t* dst, const int* srcA, const int* srcB)
{
    const float* asrc = (kc < 32) ? x : hprev;
    const float* bsrc = (kc < 32) ? W : U;
    int k0 = (kc & 31) << 5;
    const float* ap = asrc + k0;
    const float* bp = bsrc + k0;
    uint32_t sB = stage_sm + A_TILE_BYTES;
#pragma unroll
    for (int j = 0; j < 4; j++) CP_ASYNC16(stage_sm + dst[j], ap + srcA[j]);
#pragma unroll
    for (int j = 0; j < 4; j++) CP_ASYNC16(sB + dst[j], bp + srcB[j]);
}

__global__ void __launch_bounds__(NTHREADS, 2) xlstm_tf32_mma_kernel(
    const float* __restrict__ x, const float* __restrict__ hprev,
    const float* __restrict__ cprev,
    const float* __restrict__ W, const float* __restrict__ bW,
    const float* __restrict__ U, const float* __restrict__ bU,
    float* __restrict__ o1, float* __restrict__ o2, float* __restrict__ oc)
{
    extern __shared__ char smem[];
    const uint32_t sbase = smem_u32(smem);

    const int tid  = threadIdx.x;
    const int lane = tid & 31;
    const int warp = tid >> 5;
    const int warp_m = warp >> 2;      // 0..1 : 64 m-rows each
    const int warp_n = warp & 3;       // 0..3 : 8 h-cols each (x4 gates)

    const int bid = blockIdx.x;
    const int m0 = (bid >> 5) << 7;    // 64 m-tiles of 128
    const int h0 = (bid & 31) << 5;    // 32 h-tiles of 32

    // ---- cp.async per-thread offsets (slot j: row r = slot/8, 16B chunk cq) ----
    uint32_t dst[4];
    int srcA[4], srcB[4];
#pragma unroll
    for (int j = 0; j < 4; j++) {
        int slot = tid + j * NTHREADS;       // 0..1023
        int r = slot >> 3, cq = slot & 7;
        dst[j] = SWZ((uint32_t)(r * 128 + cq * 16));
        srcA[j] = (m0 + r) * 1024 + cq * 4;
        int g = r >> 5, hc = r & 31;         // B rows: gate-major [4][32]
        srcB[j] = g * 1048576 + (h0 + hc) * 1024 + cq * 4;
    }

    // ---- ldmatrix per-thread address components ----
    // All rows used by this thread have row%8 == lane%8 -> single xor value.
    const uint32_t xorv = (uint32_t)(lane & 7) << 4;
    // A (m16k8): t0=(r0-7,klo16B) t1=(r8-15,klo) t2=(r0-7,khi) t3=(r8-15,khi)
    uint32_t aOff[4];
#pragma unroll
    for (int mt = 0; mt < 4; mt++)
        aOff[mt] = (uint32_t)(warp_m * 64 + mt * 16 + (lane & 15)) * 128u;
    const uint32_t aChunkSel = (uint32_t)((lane >> 4) << 4);   // 0 or 16
    // B (n8 per gate, k16 per x4): rows = gate*32 + warp_n*8 + lane%8,
    // chunk = s2*64 + (lane>>3)*16 -> tiles t0..t3 = k-quarters 0..3.
    uint32_t bOff[4];
#pragma unroll
    for (int g = 0; g < 4; g++)
        bOff[g] = (uint32_t)(g * 32 + warp_n * 8 + (lane & 7)) * 128u;
    const uint32_t bChunkSel = (uint32_t)((lane >> 3) << 4);   // 0,16,32,48

    float acc[4][4][4];   // [mt][gate][frag]
#pragma unroll
    for (int mt = 0; mt < 4; mt++)
#pragma unroll
        for (int g = 0; g < 4; g++)
#pragma unroll
            for (int r = 0; r < 4; r++) acc[mt][g][r] = 0.0f;

    // ---- prologue: chunks 0,1 into stages 0,1 ----
    load_chunk32(0, sbase, x, hprev, W, U, dst, srcA, srcB);
    CP_COMMIT();
    load_chunk32(1, sbase + STAGE_BYTES, x, hprev, W, U, dst, srcA, srcB);
    CP_COMMIT();

    // ---- mainloop: 64 BK=32 chunks, 3 stages ----
    int cur = 0, pf = 2;   // stage of chunk kc; stage for chunk kc+2
#pragma unroll 1
    for (int kc = 0; kc < 64; kc++) {
        CP_WAIT1();          // chunk kc resident (kc+1 may still be in flight)
        __syncthreads();     // data visible to all; prev compute on pf-stage done

        if (kc + 2 < 64)
            load_chunk32(kc + 2, sbase + (uint32_t)pf * STAGE_BYTES,
                         x, hprev, W, U, dst, srcA, srcB);
        CP_COMMIT();

        const uint32_t sA = sbase + (uint32_t)cur * STAGE_BYTES;
        const uint32_t sB = sA + A_TILE_BYTES;

        uint32_t b[4][4];    // [gate][k-quarter], refreshed every 2 s-steps
#pragma unroll
        for (int s = 0; s < 4; s++) {
            if ((s & 1) == 0) {
                const uint32_t bCh = (uint32_t)((s >> 1) * 64) + bChunkSel;
#pragma unroll
                for (int g = 0; g < 4; g++)
                    LDMATRIX_X4(b[g][0], b[g][1], b[g][2], b[g][3],
                                sB + bOff[g] + (bCh ^ xorv));
            }
            const uint32_t aCh = (uint32_t)(s * 32) + aChunkSel;
            const int bsub = (s & 1) << 1;   // 0 or 2

#pragma unroll
            for (int mt = 0; mt < 4; mt++) {
                uint32_t a[4];
                LDMATRIX_X4(a[0], a[1], a[2], a[3], sA + aOff[mt] + (aCh ^ xorv));
#pragma unroll
                for (int g = 0; g < 4; g++)
                    MMA_TF32_2(acc[mt][g], a, b[g][bsub], b[g][bsub + 1]);
            }
        }

        cur = (cur == 2) ? 0 : cur + 1;
        pf  = (pf == 2) ? 0 : pf + 1;
    }

    // ---- epilogue: thread-local (all 4 gates of each (m,h) in this thread) ----
    // C frag: c0=(row l/4, col 2(l%4)); c1=+1col; c2=+8row; c3=+8row+1col
    const int hc0 = h0 + warp_n * 8 + 2 * (lane & 3);

    float bsum[4][2];
#pragma unroll
    for (int g = 0; g < 4; g++)
#pragma unroll
        for (int e = 0; e < 2; e++)
            bsum[g][e] = bW[g * 1024 + hc0 + e] + bU[g * 1024 + hc0 + e];

#pragma unroll
    for (int mt = 0; mt < 4; mt++) {
#pragma unroll
        for (int rh = 0; rh < 2; rh++) {
            int m = m0 + warp_m * 64 + mt * 16 + (lane >> 2) + rh * 8;
            size_t base = (size_t)m * 1024 + hc0;
            float2 cold = *reinterpret_cast<const float2*>(cprev + base);

            float hn[2], cn[2];
#pragma unroll
            for (int e = 0; e < 2; e++) {
                int rr = rh * 2 + e;
                float gi = acc[mt][0][rr] + bsum[0][e];
                float gf = acc[mt][1][rr] + bsum[1][e];
                float go = acc[mt][2][rr] + bsum[2][e];
                float gc = acc[mt][3][rr] + bsum[3][e];
                float iv = sigmoidf_(gi);
                float fv = sigmoidf_(gf);
                float ov = sigmoidf_(go);
                float ch = tanhf_(gc);
                float cold_e = (e == 0) ? cold.x : cold.y;
                float cv = fv * cold_e + iv * ch;
                cn[e] = cv;
                hn[e] = ov * tanhf_(cv);
            }

            float2 hv = make_float2(hn[0], hn[1]);
            *reinterpret_cast<float2*>(o1 + base) = hv;
            if (o2) *reinterpret_cast<float2*>(o2 + base) = hv;
            if (oc) *reinterpret_cast<float2*>(oc + base) = make_float2(cn[0], cn[1]);
        }
    }
}

extern "C" void kernel_launch(void* const* d_in, const int* in_sizes, int n_in,
                              void* d_out, int out_size) {
    const float* x  = (const float*)d_in[0];
    const float* h  = (const float*)d_in[1];
    const float* c  = (const float*)d_in[2];
    const float* W  = (const float*)d_in[3];
    const float* bW = (const float*)d_in[4];
    const float* U  = (const float*)d_in[5];
    const float* bU = (const float*)d_in[6];
    float* out = (float*)d_out;

    const long long BH = 8192LL * 1024LL;
    float* o1 = out;
    float* o2 = nullptr;
    float* oc = nullptr;
    if ((long long)out_size >= 3 * BH) {          // (h_new, h_new, c_new)
        o2 = out + BH;
        oc = out + 2 * BH;
    } else if ((long long)out_size >= 2 * BH) {   // (h_new, c_new)
        oc = out + BH;
    }

    cudaFuncSetAttribute(xlstm_tf32_mma_kernel,
                         cudaFuncAttributeMaxDynamicSharedMemorySize, SMEM_TOTAL);
    xlstm_tf32_mma_kernel<<<2048, NTHREADS, SMEM_TOTAL>>>(x, h, c, W, bW, U, bU, o1, o2, oc);
}